// round 1
// baseline (speedup 1.0000x reference)
#include <cuda_runtime.h>
#include <cstdint>

#define BN_SCALEF 0.9995003746877732f
#define LRELU(v) ((v) > 0.f ? (v) : 0.2f * (v))

// ---------------- scratch (device globals; no allocation) ----------------
__device__ __align__(16) float g_buf0[4 * 256 * 256 * 32]; // after conv0+pool
__device__ __align__(16) float g_buf1[4 * 128 * 128 * 32]; // after conv1+pool
__device__ __align__(16) float g_buf2[4 * 64 * 64 * 32];   // after conv2+pool / fw1
__device__ __align__(16) float g_buf3[4 * 64 * 64 * 32];   // after fw0
__device__ __align__(16) float g_disp[4 * 64 * 64 * 2];    // coarse displacement

// ---------------- layer 0: conv 3x3 (2->32) + BN + lrelu + avgpool2 ------
__global__ __launch_bounds__(256) void conv_pool_first(
    const float* __restrict__ fixedp, const float* __restrict__ movingp,
    float* __restrict__ out, const float* __restrict__ w)
{
    __shared__ float ws[9 * 2 * 32];
    for (int i = threadIdx.x; i < 576; i += blockDim.x) ws[i] = w[i];
    __syncthreads();

    const int H = 512, W = 512, Hp = 256, Wp = 256;
    int t = blockIdx.x * blockDim.x + threadIdx.x;   // one thread per conv pixel
    int q = t >> 2, r = t & 3;
    int ox = q % Wp; int tmp = q / Wp; int oy = tmp % Hp; int b = tmp / Hp;
    int cy = oy * 2 + (r >> 1), cx = ox * 2 + (r & 1);

    float acc[32];
#pragma unroll
    for (int i = 0; i < 32; i++) acc[i] = 0.f;

    const float* fb = fixedp  + (size_t)b * H * W;
    const float* mb = movingp + (size_t)b * H * W;

#pragma unroll 1
    for (int ky = 0; ky < 3; ky++) {
        int iy = cy + ky - 1;
        if (iy < 0 || iy >= H) continue;
#pragma unroll 1
        for (int kx = 0; kx < 3; kx++) {
            int ix = cx + kx - 1;
            if (ix < 0 || ix >= W) continue;
            float xf = __ldg(fb + (size_t)iy * W + ix);
            float xm = __ldg(mb + (size_t)iy * W + ix);
            const float* wp = &ws[(ky * 3 + kx) * 64];
#pragma unroll
            for (int co = 0; co < 32; co++)
                acc[co] = fmaf(xf, wp[co], fmaf(xm, wp[32 + co], acc[co]));
        }
    }

    float* ob = out + ((size_t)(b * Hp + oy) * Wp + ox) * 32;
#pragma unroll
    for (int co = 0; co < 32; co++) {
        float v = LRELU(acc[co] * BN_SCALEF);
        v += __shfl_xor_sync(0xffffffffu, v, 1);
        v += __shfl_xor_sync(0xffffffffu, v, 2);
        if (r == 0) ob[co] = 0.25f * v;
    }
}

// ---------------- conv 3x3 (32->32) + BN + lrelu + avgpool2 --------------
__global__ __launch_bounds__(256) void conv_pool32(
    const float* __restrict__ in, float* __restrict__ out,
    const float* __restrict__ w, int B, int H, int W)
{
    __shared__ float ws[9 * 32 * 32];
    for (int i = threadIdx.x; i < 9216; i += blockDim.x) ws[i] = w[i];
    __syncthreads();

    int Hp = H >> 1, Wp = W >> 1;
    int t = blockIdx.x * blockDim.x + threadIdx.x;
    int q = t >> 2, r = t & 3;
    int ox = q % Wp; int tmp = q / Wp; int oy = tmp % Hp; int b = tmp / Hp;
    int cy = oy * 2 + (r >> 1), cx = ox * 2 + (r & 1);

    float acc[32];
#pragma unroll
    for (int i = 0; i < 32; i++) acc[i] = 0.f;

    const float* inb = in + (size_t)b * H * W * 32;

#pragma unroll 1
    for (int ky = 0; ky < 3; ky++) {
        int iy = cy + ky - 1;
        if (iy < 0 || iy >= H) continue;
#pragma unroll 1
        for (int kx = 0; kx < 3; kx++) {
            int ix = cx + kx - 1;
            if (ix < 0 || ix >= W) continue;
            const float4* ip = (const float4*)(inb + ((size_t)iy * W + ix) * 32);
            const float* wp0 = &ws[(ky * 3 + kx) * 1024];
#pragma unroll 1
            for (int c4 = 0; c4 < 8; c4++) {
                float4 xv = __ldg(ip + c4);
                const float* wp = wp0 + c4 * 128;
#pragma unroll
                for (int co = 0; co < 32; co++) acc[co] = fmaf(xv.x, wp[co],       acc[co]);
#pragma unroll
                for (int co = 0; co < 32; co++) acc[co] = fmaf(xv.y, wp[32 + co],  acc[co]);
#pragma unroll
                for (int co = 0; co < 32; co++) acc[co] = fmaf(xv.z, wp[64 + co],  acc[co]);
#pragma unroll
                for (int co = 0; co < 32; co++) acc[co] = fmaf(xv.w, wp[96 + co],  acc[co]);
            }
        }
    }

    float* ob = out + ((size_t)(b * Hp + oy) * Wp + ox) * 32;
#pragma unroll
    for (int co = 0; co < 32; co++) {
        float v = LRELU(acc[co] * BN_SCALEF);
        v += __shfl_xor_sync(0xffffffffu, v, 1);
        v += __shfl_xor_sync(0xffffffffu, v, 2);
        if (r == 0) ob[co] = 0.25f * v;
    }
}

// ---------------- conv 3x3 (32->32) + BN + lrelu (no pool) ---------------
__global__ __launch_bounds__(256) void conv32(
    const float* __restrict__ in, float* __restrict__ out,
    const float* __restrict__ w, int B, int H, int W)
{
    __shared__ float ws[9 * 32 * 32];
    for (int i = threadIdx.x; i < 9216; i += blockDim.x) ws[i] = w[i];
    __syncthreads();

    int t = blockIdx.x * blockDim.x + threadIdx.x;
    int cx = t % W; int tmp = t / W; int cy = tmp % H; int b = tmp / H;

    float acc[32];
#pragma unroll
    for (int i = 0; i < 32; i++) acc[i] = 0.f;

    const float* inb = in + (size_t)b * H * W * 32;

#pragma unroll 1
    for (int ky = 0; ky < 3; ky++) {
        int iy = cy + ky - 1;
        if (iy < 0 || iy >= H) continue;
#pragma unroll 1
        for (int kx = 0; kx < 3; kx++) {
            int ix = cx + kx - 1;
            if (ix < 0 || ix >= W) continue;
            const float4* ip = (const float4*)(inb + ((size_t)iy * W + ix) * 32);
            const float* wp0 = &ws[(ky * 3 + kx) * 1024];
#pragma unroll 1
            for (int c4 = 0; c4 < 8; c4++) {
                float4 xv = __ldg(ip + c4);
                const float* wp = wp0 + c4 * 128;
#pragma unroll
                for (int co = 0; co < 32; co++) acc[co] = fmaf(xv.x, wp[co],       acc[co]);
#pragma unroll
                for (int co = 0; co < 32; co++) acc[co] = fmaf(xv.y, wp[32 + co],  acc[co]);
#pragma unroll
                for (int co = 0; co < 32; co++) acc[co] = fmaf(xv.z, wp[64 + co],  acc[co]);
#pragma unroll
                for (int co = 0; co < 32; co++) acc[co] = fmaf(xv.w, wp[96 + co],  acc[co]);
            }
        }
    }

    float* ob = out + ((size_t)(b * H + cy) * W + cx) * 32;
#pragma unroll
    for (int co = 0; co < 32; co++) ob[co] = LRELU(acc[co] * BN_SCALEF);
}

// ------- pointwise: pw0 (1x1, 32->32, lrelu, NO bn) + pw1 (32->2) --------
__global__ __launch_bounds__(256) void pointwise(
    const float* __restrict__ in, float* __restrict__ disp,
    const float* __restrict__ pw0, const float* __restrict__ pw1, int total)
{
    __shared__ float w0s[1024];
    __shared__ float w1s[64];
    for (int i = threadIdx.x; i < 1024; i += blockDim.x) w0s[i] = pw0[i];
    for (int i = threadIdx.x; i < 64; i += blockDim.x) w1s[i] = pw1[i];
    __syncthreads();

    int t = blockIdx.x * blockDim.x + threadIdx.x;
    if (t >= total) return;

    float x[32];
    const float4* ip = (const float4*)(in + (size_t)t * 32);
#pragma unroll
    for (int c4 = 0; c4 < 8; c4++) {
        float4 xv = __ldg(ip + c4);
        x[c4 * 4 + 0] = xv.x; x[c4 * 4 + 1] = xv.y;
        x[c4 * 4 + 2] = xv.z; x[c4 * 4 + 3] = xv.w;
    }
    float o0 = 0.f, o1 = 0.f;
#pragma unroll
    for (int co = 0; co < 32; co++) {
        float mid = 0.f;
#pragma unroll
        for (int ci = 0; ci < 32; ci++) mid = fmaf(x[ci], w0s[ci * 32 + co], mid);
        mid = LRELU(mid);
        o0 = fmaf(mid, w1s[co * 2 + 0], o0);
        o1 = fmaf(mid, w1s[co * 2 + 1], o1);
    }
    disp[(size_t)t * 2 + 0] = o0;
    disp[(size_t)t * 2 + 1] = o1;
}

// -------- B-spline upsample of disp (64x64 -> 512x512) + bilinear warp ---
__device__ __forceinline__ void bweights(float t, float* B)
{
    float t2 = t * t, t3 = t2 * t;
    // rows of COEFF: [-1,3,-3,1],[3,-6,3,0],[-3,0,3,0],[1,4,1,0]  (columns -> B[l])
    B[0] = -t3 + 3.f * t2 - 3.f * t + 1.f;
    B[1] = 3.f * t3 - 6.f * t2 + 4.f;
    B[2] = -3.f * t3 + 3.f * t2 + 3.f * t + 1.f;
    B[3] = t3;
}

__global__ __launch_bounds__(256) void bspline_warp(
    const float* __restrict__ disp, const float* __restrict__ movingp,
    float* __restrict__ out, int B, int H, int W)
{
    int t = blockIdx.x * blockDim.x + threadIdx.x;
    int total = B * H * W;
    if (t >= total) return;
    int x = t % W; int tmp = t / W; int y = tmp % H; int b = tmp / H;

    // _range_grid: xr[i] = clip(i/8, 0, 63);  u = xr/64
    float xr = fminf((float)x * 0.125f, 63.f);
    float yr = fminf((float)y * 0.125f, 63.f);
    int ii = (int)floorf(xr), jj = (int)floorf(yr);
    float u = xr * (1.f / 64.f), v = yr * (1.f / 64.f);

    float Bu[4], Bv[4];
    bweights(u, Bu);
    bweights(v, Bv);

    const float* db = disp + (size_t)b * 64 * 64 * 2;
    float ic0 = 0.f, ic1 = 0.f;
#pragma unroll
    for (int m = 0; m < 4; m++) {             // m indexes the j (row) offset, weighted by B_u
        int rj = jj + m - 1;
        float s0 = 0.f, s1 = 0.f;
        if (rj >= 0 && rj < 64) {
#pragma unroll
            for (int n = 0; n < 4; n++) {     // n indexes the i (col) offset, weighted by B_v
                int ri = ii + n - 1;
                if (ri >= 0 && ri < 64) {
                    const float* g = db + ((size_t)rj * 64 + ri) * 2;
                    float g0 = __ldg(g), g1 = __ldg(g + 1);
                    s0 = fmaf(Bv[n], g0, s0);
                    s1 = fmaf(Bv[n], g1, s1);
                }
            }
        }
        ic0 = fmaf(Bu[m], s0, ic0);
        ic1 = fmaf(Bu[m], s1, ic1);
    }

    float wx = ic0 + (float)x;
    float wy = ic1 + (float)y;

    // bilinear (matches reference, incl. eps division form)
    float fx = floorf(wx), fy = floorf(wy);
    float x0 = fminf(fmaxf(fx, 0.f), (float)(W - 1));
    float x1 = fminf(fmaxf(fx + 1.f, 0.f), (float)(W - 1));
    float y0 = fminf(fmaxf(fy, 0.f), (float)(H - 1));
    float y1 = fminf(fmaxf(fy + 1.f, 0.f), (float)(H - 1));
    int x0i = (int)x0, x1i = (int)x1, y0i = (int)y0, y1i = (int)y1;

    const float* im = movingp + (size_t)b * H * W;
    float Q1 = __ldg(im + (size_t)y0i * W + x0i);
    float Q2 = __ldg(im + (size_t)y1i * W + x0i);
    float Q3 = __ldg(im + (size_t)y0i * W + x1i);
    float Q4 = __ldg(im + (size_t)y1i * W + x1i);

    const float eps = 1e-5f;
    float wxr = (x1 - wx) / (x1 - x0 + eps);
    float wxl = (wx - x0) / (x1 - x0 + eps);
    float R1 = wxr * Q1 + wxl * Q3;
    float R2 = wxr * Q2 + wxl * Q4;
    float o = (y1 - wy) / (y1 - y0 + eps) * R1 + (wy - y0) / (y1 - y0 + eps) * R2;

    out[(size_t)(b * H + y) * W + x] = o;                       // warped [B,H,W,1]
    float* grid = out + (size_t)B * H * W;                      // warped_grid [B,2,H,W]
    grid[((size_t)(b * 2 + 0) * H + y) * W + x] = wx;
    grid[((size_t)(b * 2 + 1) * H + y) * W + x] = wy;
}

// --------------------------------- launch --------------------------------
extern "C" void kernel_launch(void* const* d_in, const int* in_sizes, int n_in,
                              void* d_out, int out_size)
{
    const float* fixedp  = (const float*)d_in[0];
    const float* movingp = (const float*)d_in[1];
    const float* w0  = (const float*)d_in[2];
    const float* w1  = (const float*)d_in[3];
    const float* w2  = (const float*)d_in[4];
    const float* fw0 = (const float*)d_in[5];
    const float* fw1 = (const float*)d_in[6];
    const float* pw0 = (const float*)d_in[7];
    const float* pw1 = (const float*)d_in[8];

    float *buf0, *buf1, *buf2, *buf3, *disp;
    cudaGetSymbolAddress((void**)&buf0, g_buf0);
    cudaGetSymbolAddress((void**)&buf1, g_buf1);
    cudaGetSymbolAddress((void**)&buf2, g_buf2);
    cudaGetSymbolAddress((void**)&buf3, g_buf3);
    cudaGetSymbolAddress((void**)&disp, g_disp);

    const int B = 4, H = 512, W = 512;

    // L0: 4*512*512 conv threads -> pooled [4,256,256,32]
    conv_pool_first<<<(B * H * W) / 256, 256>>>(fixedp, movingp, buf0, w0);
    // L1: input 256x256 -> pooled 128x128
    conv_pool32<<<(B * 256 * 256) / 256, 256>>>(buf0, buf1, w1, B, 256, 256);
    // L2: input 128x128 -> pooled 64x64
    conv_pool32<<<(B * 128 * 128) / 256, 256>>>(buf1, buf2, w2, B, 128, 128);
    // fw0, fw1 at 64x64 (no pool)
    conv32<<<(B * 64 * 64) / 256, 256>>>(buf2, buf3, fw0, B, 64, 64);
    conv32<<<(B * 64 * 64) / 256, 256>>>(buf3, buf2, fw1, B, 64, 64);
    // pointwise pw0+pw1 -> disp [4,64,64,2]
    pointwise<<<(B * 64 * 64) / 256, 256>>>(buf2, disp, pw0, pw1, B * 64 * 64);
    // bspline upsample + bilinear warp -> outputs
    bspline_warp<<<(B * H * W) / 256, 256>>>(disp, movingp, (float*)d_out, B, H, W);
}